// round 3
// baseline (speedup 1.0000x reference)
#include <cuda_runtime.h>
#include <math.h>

// VectorExpansion: out[l, p, n] = sin(pi*x*(n+1)) / r * fc * norm * x^l
//   x   = r / R_CUT
//   fc  = x<1 ? 0.5*(cos(pi*x)+1) : 0
//   norm = sqrt(2/R_CUT)
//
// Inputs (metadata order):
//   0 positions        [N,3]  f32
//   1 cells            [S,3,3] f32
//   2 species          [N]    i32   (unused)
//   3 cell_shifts      [P,3]  i32
//   4 centers          [N]    i32   (unused)
//   5 pairs            [P,2]  i32
//   6 structure_centers[N]    i32   (unused)
//   7 structure_pairs  [P]    i32
//   8 structure_offsets[S]    i32
// Output: [4, P, 8] f32

#define R_CUT_INV (1.0f / 5.0f)
#define NORM 0.6324555320336759f   /* sqrt(2/5) */
#define PI_F 3.14159265358979323846f

__global__ __launch_bounds__(256)
void vexp_kernel(const float*  __restrict__ pos,
                 const float*  __restrict__ cells,
                 const int*    __restrict__ shifts,
                 const int2*   __restrict__ pairs,
                 const int*    __restrict__ spair,
                 const int*    __restrict__ soff,
                 float*        __restrict__ out,
                 int P)
{
    int p = blockIdx.x * blockDim.x + threadIdx.x;
    if (p >= P) return;

    const int sp  = __ldg(&spair[p]);
    const int off = __ldg(&soff[sp]);
    const int2 pr = __ldg(&pairs[p]);

    const int sx = shifts[3 * p + 0];
    const int sy = shifts[3 * p + 1];
    const int sz = shifts[3 * p + 2];

    const float* c = cells + (size_t)sp * 9;
    const float fsx = (float)sx, fsy = (float)sy, fsz = (float)sz;

    const float* Pi = pos + (size_t)(off + pr.x) * 3;
    const float* Pj = pos + (size_t)(off + pr.y) * 3;

    float vx = __ldg(&Pj[0]) - __ldg(&Pi[0]) + fsx * __ldg(&c[0]) + fsy * __ldg(&c[3]) + fsz * __ldg(&c[6]);
    float vy = __ldg(&Pj[1]) - __ldg(&Pi[1]) + fsx * __ldg(&c[1]) + fsy * __ldg(&c[4]) + fsz * __ldg(&c[7]);
    float vz = __ldg(&Pj[2]) - __ldg(&Pi[2]) + fsx * __ldg(&c[2]) + fsy * __ldg(&c[5]) + fsz * __ldg(&c[8]);

    float r2 = fmaf(vx, vx, fmaf(vy, vy, fmaf(vz, vz, 1e-12f)));
    float r  = sqrtf(r2);
    float x  = r * R_CUT_INV;

    const size_t stride_l = (size_t)P * 8;  // floats between l-slabs
    float* obase = out + (size_t)p * 8;

    if (x >= 1.0f) {
        // fc == 0 -> all outputs exactly zero (reference multiplies by fc=0).
        float4 z = make_float4(0.f, 0.f, 0.f, 0.f);
        #pragma unroll
        for (int l = 0; l < 4; l++) {
            float4* ol = reinterpret_cast<float4*>(obase + (size_t)l * stride_l);
            ol[0] = z;
            ol[1] = z;
        }
        return;
    }

    float t  = PI_F * x;
    float c1 = __cosf(t);
    float fc = 0.5f * (c1 + 1.0f);

    float b[8];
    if (x < 0.01f) {
        // Small-r stable branch: sin(n*t)/r = (n*pi/R_CUT) * sinc(n*t)
        //   (t/r == pi/R_CUT exactly, so no catastrophic sin/r cancellation)
        // sinc(u) ~= 1 - u^2/6, truncation error < 1e-7 for u < 0.26.
        float scale = fc * NORM * (PI_F * R_CUT_INV);
        #pragma unroll
        for (int n = 1; n <= 8; n++) {
            float u = (float)n * t;
            b[n - 1] = scale * (float)n * (1.0f - u * u * (1.0f / 6.0f));
        }
    } else {
        // General branch: direct __sinf per harmonic (no recurrence -> no
        // error amplification). Abs err ~4e-7 * pref(<13) -> <1e-5.
        float pref = fc * NORM / r;
        #pragma unroll
        for (int n = 1; n <= 8; n++) {
            b[n - 1] = __sinf((float)n * t) * pref;
        }
    }

    float xl = 1.0f;
    #pragma unroll
    for (int l = 0; l < 4; l++) {
        float4* ol = reinterpret_cast<float4*>(obase + (size_t)l * stride_l);
        ol[0] = make_float4(b[0] * xl, b[1] * xl, b[2] * xl, b[3] * xl);
        ol[1] = make_float4(b[4] * xl, b[5] * xl, b[6] * xl, b[7] * xl);
        xl *= x;
    }
}

extern "C" void kernel_launch(void* const* d_in, const int* in_sizes, int n_in,
                              void* d_out, int out_size)
{
    const float* positions = (const float*)d_in[0];
    const float* cells     = (const float*)d_in[1];
    // d_in[2] species: unused
    const int*   shifts    = (const int*)  d_in[3];
    // d_in[4] centers: unused
    const int2*  pairs     = (const int2*) d_in[5];
    // d_in[6] structure_centers: unused
    const int*   spair     = (const int*)  d_in[7];
    const int*   soff      = (const int*)  d_in[8];
    float* out = (float*)d_out;

    int P = in_sizes[7];   // structure_pairs has P elements

    int threads = 256;
    int blocks  = (P + threads - 1) / threads;
    vexp_kernel<<<blocks, threads>>>(positions, cells, shifts, pairs,
                                     spair, soff, out, P);
}